// round 10
// baseline (speedup 1.0000x reference)
#include <cuda_runtime.h>
#include <cuda_fp16.h>
#include <cstdint>

#define HW    512
#define NPIX  (HW * HW)          // 262144
#define NC    64
#define MAXS  44                 // list ints/pixel: pass1 [0,9), pass2 [9, 9+35)
#define P2OFF 9
#define N2CAP (MAXS - P2OFF)     // 35; P(Poisson(9) > 35) ~ 1e-12
#define ZOFF  (NPIX * 128)       // byte offset of the zero row in g_refT

// Scratch (__device__ globals; zero-initialized at load, row NPIX never written)
__device__ __half g_refT[(size_t)(NPIX + 1) * NC];  // +1 zero row for masked slots
__device__ int    g_list[(size_t)NPIX * MAXS];      // pixel-major lists of BYTE offsets
__device__ int    g_m1[NPIX];                       // pass1 count per pixel
__device__ int    g_n2[NPIX];                       // pass2 count per pixel (atomic)

// ---------------------------------------------------------------------------
// 1) Transpose + downconvert: ref (C,H,W) fp32 -> refT (H*W, C) fp16.
//    float4 loads, uint4 (8-half) stores, 128-px tiles. Also zeroes g_n2.
// ---------------------------------------------------------------------------
__global__ __launch_bounds__(256) void transpose_ref_kernel(const float* __restrict__ ref) {
    __shared__ float tile[64][129];
    const int pixBase = blockIdx.x * 128;
    const int tid = threadIdx.x;
    const int wc = tid >> 5;      // 0..7
    const int ln = tid & 31;

    if (tid < 128) g_n2[pixBase + tid] = 0;   // fused counter reset

    #pragma unroll
    for (int it = 0; it < 8; it++) {
        const int c = wc + it * 8;
        const float4 v = __ldg((const float4*)(ref + (size_t)c * NPIX + pixBase + ln * 4));
        tile[c][ln * 4 + 0] = v.x; tile[c][ln * 4 + 1] = v.y;
        tile[c][ln * 4 + 2] = v.z; tile[c][ln * 4 + 3] = v.w;
    }
    __syncthreads();

    #pragma unroll
    for (int it = 0; it < 4; it++) {
        const int idx = tid + it * 256;
        const int px = idx >> 3;          // 0..127
        const int chunk = idx & 7;        // 8 halves per chunk
        const int c0 = chunk * 8;
        uint4 o;
        __half2 h;
        h = __float22half2_rn(make_float2(tile[c0 + 0][px], tile[c0 + 1][px]));
        o.x = *(unsigned*)&h;
        h = __float22half2_rn(make_float2(tile[c0 + 2][px], tile[c0 + 3][px]));
        o.y = *(unsigned*)&h;
        h = __float22half2_rn(make_float2(tile[c0 + 4][px], tile[c0 + 5][px]));
        o.z = *(unsigned*)&h;
        h = __float22half2_rn(make_float2(tile[c0 + 6][px], tile[c0 + 7][px]));
        o.w = *(unsigned*)&h;
        ((uint4*)(g_refT + (size_t)(pixBase + px) * NC))[chunk] = o;
    }
}

// ---------------------------------------------------------------------------
// 2) Pass-1 lists: one thread per target pixel t. Source s = t-d,
//    q = nnf_sr[s]+d. Compact valid offsets into slots [0, m1).
// ---------------------------------------------------------------------------
__global__ __launch_bounds__(256) void pass1_kernel(const int* __restrict__ nnf_sr) {
    const int t = blockIdx.x * 256 + threadIdx.x;
    const int ty = t >> 9;
    const int tx = t & (HW - 1);

    int* lst = g_list + (size_t)t * MAXS;
    int m1 = 0;

    #pragma unroll
    for (int dy = -1; dy <= 1; dy++) {
        #pragma unroll
        for (int dx = -1; dx <= 1; dx++) {
            const int sy = ty - dy, sx = tx - dx;
            if ((unsigned)sy < HW && (unsigned)sx < HW) {
                const int2 nn = __ldg(&((const int2*)nnf_sr)[sy * HW + sx]);
                const int qy = nn.x + dy, qx = nn.y + dx;
                if ((unsigned)qy < HW && (unsigned)qx < HW)
                    lst[m1++] = (qy * HW + qx) << 7;   // byte offset
            }
        }
    }
    g_m1[t] = m1;
}

// ---------------------------------------------------------------------------
// 3) Pass-2 scatter: one thread per ref pixel r. s = nnf_rs[r]; for each tap
//    d: target t = s+d, q = r+d. Append (q<<7) to t's list via atomic slot.
// ---------------------------------------------------------------------------
__global__ __launch_bounds__(256) void pass2_scatter_kernel(const int* __restrict__ nnf_rs) {
    const int r = blockIdx.x * 256 + threadIdx.x;
    const int2 nn = __ldg(&((const int2*)nnf_rs)[r]);   // (sy, sx) in [0,512)
    const int ry = r >> 9;
    const int rx = r & (HW - 1);

    #pragma unroll
    for (int dy = -1; dy <= 1; dy++) {
        #pragma unroll
        for (int dx = -1; dx <= 1; dx++) {
            const int ty = nn.x + dy, tx = nn.y + dx;
            const int qy = ry + dy,  qx = rx + dx;
            if (((unsigned)ty < HW) & ((unsigned)tx < HW) &
                ((unsigned)qy < HW) & ((unsigned)qx < HW)) {
                const int t = ty * HW + tx;
                const int slot = atomicAdd(&g_n2[t], 1);
                if (slot < N2CAP)
                    g_list[(size_t)t * MAXS + P2OFF + slot] = (qy * HW + qx) << 7;
            }
        }
    }
}

// ---------------------------------------------------------------------------
// 4) Vote: FOUR pixels per warp. Lane l serves pixel-group l>>3 with a 16-byte
//    LDG.128 (8 channels). Slots beyond the per-pixel count are SEL-masked to
//    the L1-resident zero row. Lists smem-staged, f32x2 packed accumulation.
// ---------------------------------------------------------------------------
__global__ __launch_bounds__(512) void vote_kernel(float* __restrict__ out) {
    __shared__ __align__(16) int s_list[64][MAXS];   // 64 pixels x 44 offsets
    __shared__ float s_out[64][65];
    const int tid  = threadIdx.x;
    const int warp = tid >> 5;                    // 0..15
    const int lane = tid & 31;
    const int pixBase = blockIdx.x * 64;

    // Stage 64 lists: 64 * 11 = 704 int4, coalesced.
    #pragma unroll
    for (int i = tid; i < 64 * (MAXS / 4); i += 512)
        ((int4*)s_list)[i] = __ldg(&((const int4*)g_list)[(size_t)pixBase * (MAXS / 4) + i]);
    __syncthreads();

    const int group = lane >> 3;                  // 0..3 -> pixel within warp
    const int sub   = lane & 7;                   // 16-byte chunk within row
    const int px    = warp * 4 + group;           // 0..63
    const int t     = pixBase + px;

    const int m1 = __ldg(&g_m1[t]);
    int n2 = __ldg(&g_n2[t]);
    n2 = min(n2, N2CAP);
    // warp max of n2 across the 4 groups
    int n2max = n2;
    n2max = max(n2max, __shfl_xor_sync(0xffffffffu, n2max, 8));
    n2max = max(n2max, __shfl_xor_sync(0xffffffffu, n2max, 16));

    const char* base = (const char*)g_refT + sub * 16;
    const int* row = s_list[px];

    unsigned long long a1[4] = {0ull, 0ull, 0ull, 0ull};
    unsigned long long a2[4] = {0ull, 0ull, 0ull, 0ull};

    #define ACC1(acc, u)                                                      \
    {                                                                         \
        const float2 v_ = __half22float2(*(const __half2*)&(u));              \
        unsigned long long pv_;                                               \
        asm("mov.b64 %0, {%1, %2};" : "=l"(pv_) : "f"(v_.x), "f"(v_.y));      \
        asm("add.rn.f32x2 %0, %0, %1;" : "+l"(acc) : "l"(pv_));               \
    }
    #define ACC8(acc, d) { ACC1(acc[0], (d).x); ACC1(acc[1], (d).y);          \
                           ACC1(acc[2], (d).z); ACC1(acc[3], (d).w); }

    // --- pass 1: fixed 9 slots, SEL-masked by m1, chunks of 3 ---
    #pragma unroll
    for (int jb = 0; jb < 9; jb += 3) {
        const int o0 = (jb     < m1) ? row[jb]     : (int)ZOFF;
        const int o1 = (jb + 1 < m1) ? row[jb + 1] : (int)ZOFF;
        const int o2 = (jb + 2 < m1) ? row[jb + 2] : (int)ZOFF;
        const uint4 d0 = __ldg((const uint4*)(base + o0));
        const uint4 d1 = __ldg((const uint4*)(base + o1));
        const uint4 d2 = __ldg((const uint4*)(base + o2));
        ACC8(a1, d0); ACC8(a1, d1); ACC8(a1, d2);
    }

    // --- pass 2: dynamic to warp-max, SEL-masked by n2, chunks of 2 ---
    for (int j = 0; j < n2max; j += 2) {
        const int o0 = (j     < n2) ? row[P2OFF + j]     : (int)ZOFF;
        const int o1 = (j + 1 < n2) ? row[P2OFF + j + 1] : (int)ZOFF;
        const uint4 d0 = __ldg((const uint4*)(base + o0));
        const uint4 d1 = __ldg((const uint4*)(base + o1));
        ACC8(a2, d0); ACC8(a2, d1);
    }
    #undef ACC8
    #undef ACC1

    const float ws = 1.0f / (float)NPIX;
    const float wr = 2.0f / (float)NPIX;
    const float w  = ws * (float)m1 + wr * (float)n2;
    const float inv = (w == 0.f) ? 1.f : (1.f / w);

    #pragma unroll
    for (int k = 0; k < 4; k++) {
        float2 v1, v2;
        asm("mov.b64 {%0, %1}, %2;" : "=f"(v1.x), "=f"(v1.y) : "l"(a1[k]));
        asm("mov.b64 {%0, %1}, %2;" : "=f"(v2.x), "=f"(v2.y) : "l"(a2[k]));
        s_out[px][sub * 8 + 2 * k]     = (ws * v1.x + wr * v2.x) * inv;
        s_out[px][sub * 8 + 2 * k + 1] = (ws * v1.y + wr * v2.y) * inv;
    }
    __syncthreads();

    // Writeout: 64 px x 64 ch = 4096 floats, coalesced 64-float rows.
    #pragma unroll
    for (int i = tid; i < 4096; i += 512) {
        const int c = i >> 6;
        const int p = i & 63;
        out[(size_t)c * NPIX + pixBase + p] = s_out[p][c];
    }
}

// ---------------------------------------------------------------------------
extern "C" void kernel_launch(void* const* d_in, const int* in_sizes, int n_in,
                              void* d_out, int out_size) {
    const float* ref    = (const float*)d_in[0];
    const int*   nnf_sr = (const int*)d_in[1];
    const int*   nnf_rs = (const int*)d_in[2];
    float*       out    = (float*)d_out;

    transpose_ref_kernel<<<NPIX / 128, 256>>>(ref);     // also zeroes g_n2
    pass1_kernel<<<NPIX / 256, 256>>>(nnf_sr);
    pass2_scatter_kernel<<<NPIX / 256, 256>>>(nnf_rs);
    vote_kernel<<<NPIX / 64, 512>>>(out);
}

// round 11
// speedup vs baseline: 1.2827x; 1.2827x over previous
#include <cuda_runtime.h>
#include <cuda_fp16.h>
#include <cstdint>

#define HW    512
#define NPIX  (HW * HW)          // 262144
#define NC    64
#define CAP   16                 // bucket capacity (max Poisson(1) over 262k keys ~ 10)
#define MAXS  44                 // list slots/pixel: pass1 [0,9), pass2 [9, 9+35)
#define P2OFF 9
#define ZOFF  (NPIX * 128)       // byte offset of the zero row in g_refT

// Scratch (__device__ globals; zero-initialized at load, row NPIX never written)
__device__ __half g_refT[(size_t)(NPIX + 1) * NC];  // +1 zero row for masked slots
__device__ int    g_cnt[NPIX];                      // bucket counts for inverse nnf_rs
__device__ int    g_bucket[CAP][NPIX];              // interleaved: [slot][key] -> ref pixel r
__device__ int    g_list[MAXS][NPIX];               // SLOT-MAJOR lists of BYTE offsets
__device__ int    g_counts[NPIX];                   // m1 | (n2 << 16)

// ---------------------------------------------------------------------------
// 1) Transpose + downconvert: ref (C,H,W) fp32 -> refT (H*W, C) fp16.
//    float4 loads, uint4 (8-half) stores, 128-px tiles. Also zeroes g_cnt.
// ---------------------------------------------------------------------------
__global__ __launch_bounds__(256) void transpose_ref_kernel(const float* __restrict__ ref) {
    __shared__ float tile[64][129];
    const int pixBase = blockIdx.x * 128;
    const int tid = threadIdx.x;
    const int wc = tid >> 5;      // 0..7
    const int ln = tid & 31;

    if (tid < 128) g_cnt[pixBase + tid] = 0;   // fused counter reset

    #pragma unroll
    for (int it = 0; it < 8; it++) {
        const int c = wc + it * 8;
        const float4 v = __ldg((const float4*)(ref + (size_t)c * NPIX + pixBase + ln * 4));
        tile[c][ln * 4 + 0] = v.x; tile[c][ln * 4 + 1] = v.y;
        tile[c][ln * 4 + 2] = v.z; tile[c][ln * 4 + 3] = v.w;
    }
    __syncthreads();

    #pragma unroll
    for (int it = 0; it < 4; it++) {
        const int idx = tid + it * 256;
        const int px = idx >> 3;          // 0..127
        const int chunk = idx & 7;        // 8 halves per chunk
        const int c0 = chunk * 8;
        uint4 o;
        __half2 h;
        h = __float22half2_rn(make_float2(tile[c0 + 0][px], tile[c0 + 1][px]));
        o.x = *(unsigned*)&h;
        h = __float22half2_rn(make_float2(tile[c0 + 2][px], tile[c0 + 3][px]));
        o.y = *(unsigned*)&h;
        h = __float22half2_rn(make_float2(tile[c0 + 4][px], tile[c0 + 5][px]));
        o.z = *(unsigned*)&h;
        h = __float22half2_rn(make_float2(tile[c0 + 6][px], tile[c0 + 7][px]));
        o.w = *(unsigned*)&h;
        ((uint4*)(g_refT + (size_t)(pixBase + px) * NC))[chunk] = o;
    }
}

// ---------------------------------------------------------------------------
// 2) Invert nnf_rs into buckets (262k spread atomics).
// ---------------------------------------------------------------------------
__global__ __launch_bounds__(256) void build_buckets_kernel(const int* __restrict__ nnf_rs) {
    const int r = blockIdx.x * 256 + threadIdx.x;
    const int2 nn = __ldg(&((const int2*)nnf_rs)[r]);   // (sy, sx) in [0,512)
    const int key = nn.x * HW + nn.y;
    const int slot = atomicAdd(&g_cnt[key], 1);
    if (slot < CAP) g_bucket[slot][key] = r;
}

// ---------------------------------------------------------------------------
// 3) Precompute lists: one thread per pixel, NO smem. Slot-major g_list makes
//    every list store coalesced. Pass1 -> slots [0,m1), pass2 -> [9, 9+n2).
// ---------------------------------------------------------------------------
__global__ __launch_bounds__(256) void precompute_kernel(const int* __restrict__ nnf_sr) {
    const int t = blockIdx.x * 256 + threadIdx.x;
    const int ty = t >> 9;
    const int tx = t & (HW - 1);

    int m1 = 0;            // pass1 fill [0, m1), m1 <= 9
    int p2 = P2OFF;        // pass2 fill [9, p2)

    #pragma unroll
    for (int dy = -1; dy <= 1; dy++) {
        #pragma unroll
        for (int dx = -1; dx <= 1; dx++) {
            const int sy = ty - dy, sx = tx - dx;
            if ((unsigned)sy < HW && (unsigned)sx < HW) {
                const int sidx = sy * HW + sx;

                // pass 1: s -> nnf_sr[s]+d
                const int2 nn = __ldg(&((const int2*)nnf_sr)[sidx]);
                const int qy = nn.x + dy, qx = nn.y + dx;
                if ((unsigned)qy < HW && (unsigned)qx < HW)
                    g_list[m1++][t] = (qy * HW + qx) << 7;   // coalesced store

                // pass 2: bucket entries r with nnf_rs[r] = s, q = r+d
                int n = g_cnt[sidx];
                if (n > CAP) n = CAP;
                for (int i = 0; i < n; i++) {
                    const int r = g_bucket[i][sidx];          // coalesced (interleaved)
                    const int q2y = (r >> 9) + dy, q2x = (r & (HW - 1)) + dx;
                    if (((unsigned)q2y < HW) & ((unsigned)q2x < HW) && p2 < MAXS)
                        g_list[p2++][t] = ((q2y * HW + q2x) << 7);
                }
            }
        }
    }
    g_counts[t] = m1 | ((p2 - P2OFF) << 16);
}

// ---------------------------------------------------------------------------
// 4) Vote: FOUR pixels per warp. Lane l serves pixel-group l>>3 with a 16-byte
//    LDG.128 (8 channels). Slots beyond the per-pixel count are SEL-masked to
//    the L1-resident zero row. Lists smem-staged, f32x2 packed accumulation.
// ---------------------------------------------------------------------------
__global__ __launch_bounds__(512) void vote_kernel(float* __restrict__ out) {
    __shared__ __align__(16) int s_list[MAXS * 64];   // [slot][px], 11 KB
    __shared__ float s_out[64][65];
    const int tid  = threadIdx.x;
    const int warp = tid >> 5;                    // 0..15
    const int lane = tid & 31;
    const int pixBase = blockIdx.x * 64;

    // Stage 44 slot-rows of 64 ints each (16 int4 per row), coalesced.
    #pragma unroll
    for (int i = tid; i < MAXS * 16; i += 512) {
        const int j = i >> 4;                     // slot row
        const int k = i & 15;                     // int4 within row
        ((int4*)s_list)[i] = __ldg(((const int4*)(&g_list[j][pixBase])) + k);
    }
    __syncthreads();

    const int group = lane >> 3;                  // 0..3 -> pixel within warp
    const int sub   = lane & 7;                   // 16-byte chunk within row
    const int px    = warp * 4 + group;           // 0..63
    const int t     = pixBase + px;

    const int packed = __ldg(&g_counts[t]);
    const int m1 = packed & 0xffff;
    const int n2 = packed >> 16;
    // warp max of n2 across the 4 groups
    int n2max = n2;
    n2max = max(n2max, __shfl_xor_sync(0xffffffffu, n2max, 8));
    n2max = max(n2max, __shfl_xor_sync(0xffffffffu, n2max, 16));

    const char* base = (const char*)g_refT + sub * 16;
    const int* col = s_list + px;                 // entry j at col[j * 64]

    unsigned long long a1[4] = {0ull, 0ull, 0ull, 0ull};
    unsigned long long a2[4] = {0ull, 0ull, 0ull, 0ull};

    #define ACC1(acc, u)                                                      \
    {                                                                         \
        const float2 v_ = __half22float2(*(const __half2*)&(u));              \
        unsigned long long pv_;                                               \
        asm("mov.b64 %0, {%1, %2};" : "=l"(pv_) : "f"(v_.x), "f"(v_.y));      \
        asm("add.rn.f32x2 %0, %0, %1;" : "+l"(acc) : "l"(pv_));               \
    }
    #define ACC8(acc, d) { ACC1(acc[0], (d).x); ACC1(acc[1], (d).y);          \
                           ACC1(acc[2], (d).z); ACC1(acc[3], (d).w); }

    // --- pass 1: fixed 9 slots, SEL-masked by m1, chunks of 3 ---
    #pragma unroll
    for (int jb = 0; jb < 9; jb += 3) {
        const int o0 = (jb     < m1) ? col[(jb    ) * 64] : (int)ZOFF;
        const int o1 = (jb + 1 < m1) ? col[(jb + 1) * 64] : (int)ZOFF;
        const int o2 = (jb + 2 < m1) ? col[(jb + 2) * 64] : (int)ZOFF;
        const uint4 d0 = __ldg((const uint4*)(base + o0));
        const uint4 d1 = __ldg((const uint4*)(base + o1));
        const uint4 d2 = __ldg((const uint4*)(base + o2));
        ACC8(a1, d0); ACC8(a1, d1); ACC8(a1, d2);
    }

    // --- pass 2: dynamic to warp-max, SEL-masked by n2, chunks of 2 ---
    for (int j = 0; j < n2max; j += 2) {
        const int o0 = (j     < n2) ? col[(P2OFF + j    ) * 64] : (int)ZOFF;
        const int o1 = (j + 1 < n2) ? col[(P2OFF + j + 1) * 64] : (int)ZOFF;
        const uint4 d0 = __ldg((const uint4*)(base + o0));
        const uint4 d1 = __ldg((const uint4*)(base + o1));
        ACC8(a2, d0); ACC8(a2, d1);
    }
    #undef ACC8
    #undef ACC1

    const float ws = 1.0f / (float)NPIX;
    const float wr = 2.0f / (float)NPIX;
    const float w  = ws * (float)m1 + wr * (float)n2;
    const float inv = (w == 0.f) ? 1.f : (1.f / w);

    #pragma unroll
    for (int k = 0; k < 4; k++) {
        float2 v1, v2;
        asm("mov.b64 {%0, %1}, %2;" : "=f"(v1.x), "=f"(v1.y) : "l"(a1[k]));
        asm("mov.b64 {%0, %1}, %2;" : "=f"(v2.x), "=f"(v2.y) : "l"(a2[k]));
        s_out[px][sub * 8 + 2 * k]     = (ws * v1.x + wr * v2.x) * inv;
        s_out[px][sub * 8 + 2 * k + 1] = (ws * v1.y + wr * v2.y) * inv;
    }
    __syncthreads();

    // Writeout: 64 px x 64 ch = 4096 floats, coalesced 64-float rows.
    #pragma unroll
    for (int i = tid; i < 4096; i += 512) {
        const int c = i >> 6;
        const int p = i & 63;
        out[(size_t)c * NPIX + pixBase + p] = s_out[p][c];
    }
}

// ---------------------------------------------------------------------------
extern "C" void kernel_launch(void* const* d_in, const int* in_sizes, int n_in,
                              void* d_out, int out_size) {
    const float* ref    = (const float*)d_in[0];
    const int*   nnf_sr = (const int*)d_in[1];
    const int*   nnf_rs = (const int*)d_in[2];
    float*       out    = (float*)d_out;

    transpose_ref_kernel<<<NPIX / 128, 256>>>(ref);     // also zeroes g_cnt
    build_buckets_kernel<<<NPIX / 256, 256>>>(nnf_rs);
    precompute_kernel<<<NPIX / 256, 256>>>(nnf_sr);
    vote_kernel<<<NPIX / 64, 512>>>(out);
}